// round 2
// baseline (speedup 1.0000x reference)
#include <cuda_runtime.h>
#include <cstdint>

#define BB    8192
#define CC    1024
#define NCLS  100
#define CAP   1024
#define MAXT  8          // supports class sizes up to 256
#define NPAIRS 36        // 8*9/2 tile-pairs
#define TINV  0.25f      // 1/T, T=4

// ---- scratch (device globals: no allocations allowed) ----
__device__ float g_probs[(size_t)BB * CC];     // 32 MB
__device__ float g_t[BB];
__device__ int   g_cnt[NCLS];
__device__ int   g_list[NCLS * CAP];
__device__ float g_partial[NCLS * NPAIRS];
__device__ int   g_stride;                     // 1 = int32 targets, 2 = int64 (low words)

__device__ __forceinline__ float warpMaxf(float v) {
#pragma unroll
  for (int o = 16; o > 0; o >>= 1) v = fmaxf(v, __shfl_xor_sync(0xffffffffu, v, o));
  return v;
}
__device__ __forceinline__ float warpSumf(float v) {
#pragma unroll
  for (int o = 16; o > 0; o >>= 1) v += __shfl_xor_sync(0xffffffffu, v, o);
  return v;
}

// exp(z) for z <= 0 via 2^w with degree-7 poly on f in [0,1): FMA pipe only,
// avoids MUFU.EX2 (rt 8/SMSP would dominate). Rel err ~2e-6.
__device__ __forceinline__ float fast_exp(float z) {
  float w  = z * 1.4426950408889634f;
  float nf = floorf(w);
  float f  = w - nf;
  float r  = 1.5252733e-5f;
  r = fmaf(r, f, 1.5403530e-4f);
  r = fmaf(r, f, 1.3333558e-3f);
  r = fmaf(r, f, 9.6181291e-3f);
  r = fmaf(r, f, 5.5504109e-2f);
  r = fmaf(r, f, 2.4022651e-1f);
  r = fmaf(r, f, 6.9314718e-1f);
  r = fmaf(r, f, 1.0f);
  return r * __int_as_float(((int)nf + 127) << 23);
}

// ---------------- init ----------------
__global__ void init_kernel() {
  int i = blockIdx.x * blockDim.x + threadIdx.x;
  if (i < NCLS) g_cnt[i] = 0;
  if (i < NCLS * NPAIRS) g_partial[i] = 0.0f;
}

// ---------------- target dtype probe ----------------
// JAX with x64 disabled silently stores int64-requested targets as int32.
// If the buffer were true little-endian int64 with values in [0,100), every
// odd 32-bit word of the first BB words would be 0. If int32, odd words are
// targets (nonzero w.h.p. ~ 1 - 0.01^4096). Reading BB ints is safe for both.
__global__ void detect_kernel(const int* __restrict__ tgt32) {
  __shared__ int nz;
  if (threadIdx.x == 0) nz = 0;
  __syncthreads();
  int cnt = 0;
  for (int i = threadIdx.x; i < BB / 2; i += blockDim.x)
    if (tgt32[2 * i + 1] != 0) cnt++;
  atomicAdd(&nz, cnt);
  __syncthreads();
  if (threadIdx.x == 0) g_stride = (nz == 0) ? 2 : 1;
}

// ---------------- softmax + t ----------------
// One CTA per row, 256 threads, 4 elems/thread (float4).
__global__ void softmax_kernel(const float* __restrict__ x) {
  int row = blockIdx.x;
  int tid = threadIdx.x;
  __shared__ float red[8];
  __shared__ float sM, sS;

  const float4 xv = reinterpret_cast<const float4*>(x + (size_t)row * CC)[tid];
  float y0 = xv.x * TINV, y1 = xv.y * TINV, y2 = xv.z * TINV, y3 = xv.w * TINV;

  float m = fmaxf(fmaxf(y0, y1), fmaxf(y2, y3));
  m = warpMaxf(m);
  if ((tid & 31) == 0) red[tid >> 5] = m;
  __syncthreads();
  if (tid < 32) {
    float v = (tid < 8) ? red[tid] : -3.4e38f;
    v = warpMaxf(v);
    if (tid == 0) sM = v;
  }
  __syncthreads();
  float M = sM;

  float e0 = fast_exp(y0 - M), e1 = fast_exp(y1 - M);
  float e2 = fast_exp(y2 - M), e3 = fast_exp(y3 - M);
  float s = (e0 + e1) + (e2 + e3);
  s = warpSumf(s);
  if ((tid & 31) == 0) red[tid >> 5] = s;
  __syncthreads();
  if (tid < 32) {
    float v = (tid < 8) ? red[tid] : 0.0f;
    v = warpSumf(v);
    if (tid == 0) sS = v;
  }
  __syncthreads();
  float S    = sS;
  float invS = 1.0f / S;
  float lnS  = __logf(S);

  float p0 = fmaf(e0, invS, 1e-8f), p1 = fmaf(e1, invS, 1e-8f);
  float p2 = fmaf(e2, invS, 1e-8f), p3 = fmaf(e3, invS, 1e-8f);
  float4 pv = make_float4(p0, p1, p2, p3);
  reinterpret_cast<float4*>(g_probs + (size_t)row * CC)[tid] = pv;

  // log p ~= (y - M - lnS); the +1e-8 shift perturbs log by ~1e-5 abs -> negligible
  float tl = p0 * (y0 - M - lnS) + p1 * (y1 - M - lnS)
           + p2 * (y2 - M - lnS) + p3 * (y3 - M - lnS);
  tl = warpSumf(tl);
  if ((tid & 31) == 0) red[tid >> 5] = tl;
  __syncthreads();
  if (tid < 32) {
    float v = (tid < 8) ? red[tid] : 0.0f;
    v = warpSumf(v);
    if (tid == 0) g_t[row] = v * (1.0f / CC);
  }
}

// ---------------- scatter by class ----------------
__global__ void scatter_kernel(const int* __restrict__ tgt32) {
  int i = blockIdx.x * blockDim.x + threadIdx.x;
  if (i < BB) {
    int c = tgt32[(size_t)i * g_stride];  // stride 2 picks int64 low words
    if ((unsigned)c < NCLS) {
      int s = atomicAdd(&g_cnt[c], 1);
      if (s < CAP) g_list[c * CAP + s] = i;
    }
  }
}

// ---------------- per-class Gram + masked kl^2 ----------------
// blockIdx.y = class, blockIdx.x = tile-pair (ti<=tj over up to 8 tiles of 32).
// 64 threads (8x8), each computes a 4x4 block of pair dot-products.
__global__ void gram_kernel() {
  int c = blockIdx.y;
  int p = blockIdx.x;
  int g = g_cnt[c];

  int ti = 0, rem = p;
  while (rem >= MAXT - ti) { rem -= MAXT - ti; ti++; }
  int tj = ti + rem;
  int ntiles = (g + 31) >> 5;
  if (g < 2 || tj >= ntiles) return;

  __shared__ float sA[32][132];   // row-major, pad 132 (16B aligned rows)
  __shared__ float sB[32][132];
  __shared__ int   sRA[32], sRB[32];

  int tid = threadIdx.x;          // 0..63
  int ii = tid & 7, jj = tid >> 3;
  int lbase = c * CAP;

  if (tid < 32) {
    int mA = ti * 32 + tid;
    sRA[tid] = g_list[lbase + min(mA, g - 1)];
  } else {
    int t2 = tid - 32;
    int mB = tj * 32 + t2;
    sRB[t2] = g_list[lbase + min(mB, g - 1)];
  }

  float acc[4][4];
#pragma unroll
  for (int a = 0; a < 4; a++)
#pragma unroll
    for (int b = 0; b < 4; b++) acc[a][b] = 0.0f;

  for (int kb = 0; kb < CC; kb += 128) {
    __syncthreads();   // protects sRA first iter + previous-chunk reads
#pragma unroll 4
    for (int q = 0; q < 16; q++) {
      int idx4 = tid + 64 * q;           // 0..1023 float4 slots (32 rows x 32)
      int row  = idx4 >> 5;
      int c4   = idx4 & 31;
      const float4 va = *reinterpret_cast<const float4*>(
          g_probs + (size_t)sRA[row] * CC + kb + c4 * 4);
      *reinterpret_cast<float4*>(&sA[row][c4 * 4]) = va;
      const float4 vb = *reinterpret_cast<const float4*>(
          g_probs + (size_t)sRB[row] * CC + kb + c4 * 4);
      *reinterpret_cast<float4*>(&sB[row][c4 * 4]) = vb;
    }
    __syncthreads();

#pragma unroll 2
    for (int k4 = 0; k4 < 128; k4 += 4) {
      float4 av[4], bv[4];
#pragma unroll
      for (int a = 0; a < 4; a++)
        av[a] = *reinterpret_cast<const float4*>(&sA[ii + 8 * a][k4]);
#pragma unroll
      for (int b = 0; b < 4; b++)
        bv[b] = *reinterpret_cast<const float4*>(&sB[jj + 8 * b][k4]);
#pragma unroll
      for (int a = 0; a < 4; a++)
#pragma unroll
        for (int b = 0; b < 4; b++) {
          acc[a][b] = fmaf(av[a].x, bv[b].x, acc[a][b]);
          acc[a][b] = fmaf(av[a].y, bv[b].y, acc[a][b]);
          acc[a][b] = fmaf(av[a].z, bv[b].z, acc[a][b]);
          acc[a][b] = fmaf(av[a].w, bv[b].w, acc[a][b]);
        }
    }
  }

  // each unordered pair contributes (t_i - c)^2 + (t_j - c)^2 (both orders)
  float local = 0.0f;
#pragma unroll
  for (int a = 0; a < 4; a++) {
    int locA = ii + 8 * a;
    int mA   = ti * 32 + locA;
    if (mA >= g) continue;
    float tAv = g_t[sRA[locA]];
#pragma unroll
    for (int b = 0; b < 4; b++) {
      int locB = jj + 8 * b;
      int mB   = tj * 32 + locB;
      if (mB >= g) continue;
      if (ti == tj && mA >= mB) continue;  // diagonal tile: i<j once
      float cr = acc[a][b] * (1.0f / (float)CC);
      float tBv = g_t[sRB[locB]];
      float d1 = tAv - cr;
      float d2 = tBv - cr;
      local += d1 * d1 + d2 * d2;
    }
  }

  local = warpSumf(local);
  __shared__ float rsum[2];
  if ((tid & 31) == 0) rsum[tid >> 5] = local;
  __syncthreads();
  if (tid == 0) g_partial[c * NPAIRS + p] = rsum[0] + rsum[1];
}

// ---------------- final reduce ----------------
__global__ void final_kernel(float* __restrict__ out) {
  int tid = threadIdx.x;  // 256
  float s = 0.0f;
  for (int i = tid; i < NCLS * NPAIRS; i += 256) s += g_partial[i];
  s = warpSumf(s);
  __shared__ float red[8];
  if ((tid & 31) == 0) red[tid >> 5] = s;
  __syncthreads();
  if (tid == 0) {
    float tot = 0.0f;
#pragma unroll
    for (int w = 0; w < 8; w++) tot += red[w];
    out[0] = tot / (float)BB;
  }
}

extern "C" void kernel_launch(void* const* d_in, const int* in_sizes, int n_in,
                              void* d_out, int out_size) {
  const float* x;
  const int* tgt32;
  if (in_sizes[0] == BB) {       // defensive input-order detection
    tgt32 = (const int*)d_in[0];
    x     = (const float*)d_in[1];
  } else {
    x     = (const float*)d_in[0];
    tgt32 = (const int*)d_in[1];
  }

  init_kernel<<<(NCLS * NPAIRS + 255) / 256, 256>>>();
  detect_kernel<<<1, 256>>>(tgt32);
  softmax_kernel<<<BB, 256>>>(x);
  scatter_kernel<<<(BB + 255) / 256, 256>>>(tgt32);
  dim3 gg(NPAIRS, NCLS);
  gram_kernel<<<gg, 64>>>();
  final_kernel<<<1, 256>>>((float*)d_out);
}

// round 3
// speedup vs baseline: 1.3920x; 1.3920x over previous
#include <cuda_runtime.h>
#include <cstdint>

#define BB    8192
#define CC    1024
#define NCLS  100
#define CAP   1024
#define MAXT  8          // supports class sizes up to 256
#define NPAIRS 36        // 8*9/2 tile-pairs
#define TINV  0.25f      // 1/T, T=4
#define KCH   64         // K chunk per pipeline stage
#define NCHUNK (CC / KCH)
#define SPAD  68         // 64 + 4 pad: conflict-free 16B row access

// ---- scratch (device globals: no allocations allowed) ----
__device__ float g_probs[(size_t)BB * CC];     // 32 MB
__device__ float g_t[BB];
__device__ int   g_cnt[NCLS];
__device__ int   g_list[NCLS * CAP];
__device__ float g_partial[NCLS * NPAIRS];

__device__ __forceinline__ float warpMaxf(float v) {
#pragma unroll
  for (int o = 16; o > 0; o >>= 1) v = fmaxf(v, __shfl_xor_sync(0xffffffffu, v, o));
  return v;
}
__device__ __forceinline__ float warpSumf(float v) {
#pragma unroll
  for (int o = 16; o > 0; o >>= 1) v += __shfl_xor_sync(0xffffffffu, v, o);
  return v;
}

// packed fp32x2 FMA: d = a*b + d (2 MACs per issue slot on sm_103a)
__device__ __forceinline__ void ffma2(unsigned long long& d,
                                      unsigned long long a,
                                      unsigned long long b) {
  asm("fma.rn.f32x2 %0, %1, %2, %0;" : "+l"(d) : "l"(a), "l"(b));
}

__device__ __forceinline__ void cp_async16(void* smem, const void* gmem) {
  unsigned s = (unsigned)__cvta_generic_to_shared(smem);
  asm volatile("cp.async.cg.shared.global [%0], [%1], 16;" :: "r"(s), "l"(gmem));
}
__device__ __forceinline__ void cp_commit() {
  asm volatile("cp.async.commit_group;");
}
template <int N>
__device__ __forceinline__ void cp_wait() {
  asm volatile("cp.async.wait_group %0;" :: "n"(N));
}

// exp(z) for z <= 0 via 2^w with degree-7 poly: FMA pipe only, avoids MUFU.EX2.
__device__ __forceinline__ float fast_exp(float z) {
  float w  = z * 1.4426950408889634f;
  float nf = floorf(w);
  float f  = w - nf;
  float r  = 1.5252733e-5f;
  r = fmaf(r, f, 1.5403530e-4f);
  r = fmaf(r, f, 1.3333558e-3f);
  r = fmaf(r, f, 9.6181291e-3f);
  r = fmaf(r, f, 5.5504109e-2f);
  r = fmaf(r, f, 2.4022651e-1f);
  r = fmaf(r, f, 6.9314718e-1f);
  r = fmaf(r, f, 1.0f);
  return r * __int_as_float(((int)nf + 127) << 23);
}

// ---------------- setup: init + dtype probe + class scatter (one CTA) ----------------
// JAX with x64 disabled silently stores int64-requested targets as int32.
// True LE int64 in [0,100) => every odd 32-bit word of the first BB words is 0.
__global__ void setup_kernel(const int* __restrict__ tgt32) {
  __shared__ int scnt[NCLS];
  __shared__ int nz;
  int tid = threadIdx.x;  // 1024

  for (int i = tid; i < NCLS; i += 1024) scnt[i] = 0;
  for (int i = tid; i < NCLS * NPAIRS; i += 1024) g_partial[i] = 0.0f;
  if (tid == 0) nz = 0;
  __syncthreads();

  int c = 0;
  for (int i = tid; i < BB / 2; i += 1024)
    if (tgt32[2 * i + 1] != 0) c++;
  if (c) atomicAdd(&nz, 1);
  __syncthreads();
  int stride = (nz == 0) ? 2 : 1;   // 2 => int64 low words

  for (int i = tid; i < BB; i += 1024) {
    int cl = tgt32[(size_t)i * stride];
    if ((unsigned)cl < NCLS) {
      int s = atomicAdd(&scnt[cl], 1);
      if (s < CAP) g_list[cl * CAP + s] = i;
    }
  }
  __syncthreads();
  for (int i = tid; i < NCLS; i += 1024) g_cnt[i] = scnt[i];
}

// ---------------- softmax + t ----------------
__global__ void softmax_kernel(const float* __restrict__ x) {
  int row = blockIdx.x;
  int tid = threadIdx.x;
  __shared__ float red[8];
  __shared__ float sM, sS;

  const float4 xv = reinterpret_cast<const float4*>(x + (size_t)row * CC)[tid];
  float y0 = xv.x * TINV, y1 = xv.y * TINV, y2 = xv.z * TINV, y3 = xv.w * TINV;

  float m = fmaxf(fmaxf(y0, y1), fmaxf(y2, y3));
  m = warpMaxf(m);
  if ((tid & 31) == 0) red[tid >> 5] = m;
  __syncthreads();
  if (tid < 32) {
    float v = (tid < 8) ? red[tid] : -3.4e38f;
    v = warpMaxf(v);
    if (tid == 0) sM = v;
  }
  __syncthreads();
  float M = sM;

  float e0 = fast_exp(y0 - M), e1 = fast_exp(y1 - M);
  float e2 = fast_exp(y2 - M), e3 = fast_exp(y3 - M);
  float s = (e0 + e1) + (e2 + e3);
  s = warpSumf(s);
  if ((tid & 31) == 0) red[tid >> 5] = s;
  __syncthreads();
  if (tid < 32) {
    float v = (tid < 8) ? red[tid] : 0.0f;
    v = warpSumf(v);
    if (tid == 0) sS = v;
  }
  __syncthreads();
  float S    = sS;
  float invS = 1.0f / S;
  float lnS  = __logf(S);

  float p0 = fmaf(e0, invS, 1e-8f), p1 = fmaf(e1, invS, 1e-8f);
  float p2 = fmaf(e2, invS, 1e-8f), p3 = fmaf(e3, invS, 1e-8f);
  reinterpret_cast<float4*>(g_probs + (size_t)row * CC)[tid] =
      make_float4(p0, p1, p2, p3);

  float tl = p0 * (y0 - M - lnS) + p1 * (y1 - M - lnS)
           + p2 * (y2 - M - lnS) + p3 * (y3 - M - lnS);
  tl = warpSumf(tl);
  if ((tid & 31) == 0) red[tid >> 5] = tl;
  __syncthreads();
  if (tid < 32) {
    float v = (tid < 8) ? red[tid] : 0.0f;
    v = warpSumf(v);
    if (tid == 0) g_t[row] = v * (1.0f / CC);
  }
}

// ---------------- per-class Gram + masked kl^2 ----------------
// blockIdx.y = class, blockIdx.x = tile-pair (ti<=tj over up to 8 tiles of 32).
// 64 threads (8x8), 4x4 register block, fp32x2 packed FMA, cp.async 2-stage pipe.
__global__ void __launch_bounds__(64) gram_kernel() {
  int c = blockIdx.y;
  int p = blockIdx.x;
  int g = g_cnt[c];

  int ti = 0, rem = p;
  while (rem >= MAXT - ti) { rem -= MAXT - ti; ti++; }
  int tj = ti + rem;
  int ntiles = (g + 31) >> 5;
  if (g < 2 || tj >= ntiles) return;

  __shared__ float sA[2][32][SPAD];
  __shared__ float sB[2][32][SPAD];
  __shared__ int   sRA[32], sRB[32];

  int tid = threadIdx.x;          // 0..63
  int ii = tid & 7, jj = tid >> 3;
  int lbase = c * CAP;

  if (tid < 32) {
    sRA[tid] = g_list[lbase + min(ti * 32 + tid, g - 1)];
  } else {
    int t2 = tid - 32;
    sRB[t2] = g_list[lbase + min(tj * 32 + t2, g - 1)];
  }
  __syncthreads();

  // load one KCH-chunk (both tiles) into stage st via cp.async
  auto load_chunk = [&](int st, int kb) {
#pragma unroll
    for (int q = 0; q < 8; q++) {
      int idx4 = tid + 64 * q;          // 0..511: 32 rows x 16 float4
      int row  = idx4 >> 4;
      int c4   = idx4 & 15;
      cp_async16(&sA[st][row][c4 * 4],
                 g_probs + (size_t)sRA[row] * CC + kb + c4 * 4);
      cp_async16(&sB[st][row][c4 * 4],
                 g_probs + (size_t)sRB[row] * CC + kb + c4 * 4);
    }
  };

  unsigned long long acc[4][4];
#pragma unroll
  for (int a = 0; a < 4; a++)
#pragma unroll
    for (int b = 0; b < 4; b++) acc[a][b] = 0ull;

  load_chunk(0, 0);
  cp_commit();

  for (int ch = 0; ch < NCHUNK; ch++) {
    if (ch + 1 < NCHUNK) {
      load_chunk((ch + 1) & 1, (ch + 1) * KCH);
      cp_commit();
      cp_wait<1>();
    } else {
      cp_wait<0>();
    }
    __syncthreads();

    int st = ch & 1;
#pragma unroll
    for (int k4 = 0; k4 < KCH; k4 += 4) {
      ulonglong2 av[4], bv[4];
#pragma unroll
      for (int a = 0; a < 4; a++)
        av[a] = *reinterpret_cast<const ulonglong2*>(&sA[st][ii + 8 * a][k4]);
#pragma unroll
      for (int b = 0; b < 4; b++)
        bv[b] = *reinterpret_cast<const ulonglong2*>(&sB[st][jj + 8 * b][k4]);
#pragma unroll
      for (int a = 0; a < 4; a++)
#pragma unroll
        for (int b = 0; b < 4; b++) {
          ffma2(acc[a][b], av[a].x, bv[b].x);
          ffma2(acc[a][b], av[a].y, bv[b].y);
        }
    }
    __syncthreads();  // buffer st fully consumed before it is refilled
  }

  // each unordered pair contributes (t_i - c)^2 + (t_j - c)^2 (both orders)
  float local = 0.0f;
#pragma unroll
  for (int a = 0; a < 4; a++) {
    int locA = ii + 8 * a;
    int mA   = ti * 32 + locA;
    if (mA >= g) continue;
    float tAv = g_t[sRA[locA]];
#pragma unroll
    for (int b = 0; b < 4; b++) {
      int locB = jj + 8 * b;
      int mB   = tj * 32 + locB;
      if (mB >= g) continue;
      if (ti == tj && mA >= mB) continue;  // diagonal tile: i<j once
      unsigned long long v = acc[a][b];
      float dot = __uint_as_float((unsigned)v) +
                  __uint_as_float((unsigned)(v >> 32));
      float cr  = dot * (1.0f / (float)CC);
      float tBv = g_t[sRB[locB]];
      float d1 = tAv - cr;
      float d2 = tBv - cr;
      local += d1 * d1 + d2 * d2;
    }
  }

  local = warpSumf(local);
  __shared__ float rsum[2];
  if ((tid & 31) == 0) rsum[tid >> 5] = local;
  __syncthreads();
  if (tid == 0) g_partial[c * NPAIRS + p] = rsum[0] + rsum[1];
}

// ---------------- final reduce ----------------
__global__ void final_kernel(float* __restrict__ out) {
  int tid = threadIdx.x;  // 256
  float s = 0.0f;
  for (int i = tid; i < NCLS * NPAIRS; i += 256) s += g_partial[i];
  s = warpSumf(s);
  __shared__ float red[8];
  if ((tid & 31) == 0) red[tid >> 5] = s;
  __syncthreads();
  if (tid == 0) {
    float tot = 0.0f;
#pragma unroll
    for (int w = 0; w < 8; w++) tot += red[w];
    out[0] = tot / (float)BB;
  }
}

extern "C" void kernel_launch(void* const* d_in, const int* in_sizes, int n_in,
                              void* d_out, int out_size) {
  const float* x;
  const int* tgt32;
  if (in_sizes[0] == BB) {       // defensive input-order detection
    tgt32 = (const int*)d_in[0];
    x     = (const float*)d_in[1];
  } else {
    x     = (const float*)d_in[0];
    tgt32 = (const int*)d_in[1];
  }

  setup_kernel<<<1, 1024>>>(tgt32);
  softmax_kernel<<<BB, 256>>>(x);
  dim3 gg(NPAIRS, NCLS);
  gram_kernel<<<gg, 64>>>();
  final_kernel<<<1, 256>>>((float*)d_out);
}

// round 5
// speedup vs baseline: 3.1638x; 2.2728x over previous
#include <cuda_runtime.h>
#include <cuda_bf16.h>
#include <cstdint>

#define BB    8192
#define CC    1024
#define NCLS  100
#define CAP   1024
#define NTP   3          // block pairs (0,0),(0,1),(1,1): class size <= 256
#define TINV  0.25f      // 1/T, T=4
#define KC    64         // bf16 per K-chunk (128 bytes/row)
#define NCHUNK (CC / KC) // 16

// ---- scratch (device globals: no allocations allowed) ----
__device__ __nv_bfloat16 g_pb[(size_t)BB * CC];   // 16 MB bf16 probs
__device__ float g_t[BB];
__device__ int   g_cnt[NCLS];
__device__ int   g_list[NCLS * CAP];
__device__ float g_partial[NCLS * NTP];

// ---- helpers ----
__device__ __forceinline__ uint32_t smem_u32(const void* p) {
  uint32_t a;
  asm("{ .reg .u64 t; cvta.to.shared.u64 t, %1; cvt.u32.u64 %0, t; }" : "=r"(a) : "l"(p));
  return a;
}
__device__ __forceinline__ void cpa16(uint32_t smem_dst, const void* gsrc) {
  asm volatile("cp.async.cg.shared.global [%0], [%1], 16;" :: "r"(smem_dst), "l"(gsrc));
}
__device__ __forceinline__ void cp_commit() { asm volatile("cp.async.commit_group;"); }
template <int N> __device__ __forceinline__ void cp_wait() {
  asm volatile("cp.async.wait_group %0;" :: "n"(N));
}
__device__ __forceinline__ uint32_t swz(uint32_t b) { return b ^ ((b >> 3) & 0x70); }

__device__ __forceinline__ void ldsm_x4(uint32_t a, uint32_t& r0, uint32_t& r1,
                                        uint32_t& r2, uint32_t& r3) {
  asm volatile("ldmatrix.sync.aligned.m8n8.x4.shared.b16 {%0,%1,%2,%3}, [%4];"
               : "=r"(r0), "=r"(r1), "=r"(r2), "=r"(r3) : "r"(a));
}
__device__ __forceinline__ void mma16816(float* c, uint32_t a0, uint32_t a1,
                                         uint32_t a2, uint32_t a3,
                                         uint32_t b0, uint32_t b1) {
  asm volatile(
      "mma.sync.aligned.m16n8k16.row.col.f32.bf16.bf16.f32 "
      "{%0,%1,%2,%3}, {%4,%5,%6,%7}, {%8,%9}, {%0,%1,%2,%3};"
      : "+f"(c[0]), "+f"(c[1]), "+f"(c[2]), "+f"(c[3])
      : "r"(a0), "r"(a1), "r"(a2), "r"(a3), "r"(b0), "r"(b1));
}

__device__ __forceinline__ float warpMaxf(float v) {
#pragma unroll
  for (int o = 16; o > 0; o >>= 1) v = fmaxf(v, __shfl_xor_sync(0xffffffffu, v, o));
  return v;
}
__device__ __forceinline__ float warpSumf(float v) {
#pragma unroll
  for (int o = 16; o > 0; o >>= 1) v += __shfl_xor_sync(0xffffffffu, v, o);
  return v;
}

// exp(z) for z <= 0 via 2^w with degree-7 poly: FMA pipe only, avoids MUFU.EX2.
__device__ __forceinline__ float fast_exp(float z) {
  float w  = z * 1.4426950408889634f;
  float nf = floorf(w);
  float f  = w - nf;
  float r  = 1.5252733e-5f;
  r = fmaf(r, f, 1.5403530e-4f);
  r = fmaf(r, f, 1.3333558e-3f);
  r = fmaf(r, f, 9.6181291e-3f);
  r = fmaf(r, f, 5.5504109e-2f);
  r = fmaf(r, f, 2.4022651e-1f);
  r = fmaf(r, f, 6.9314718e-1f);
  r = fmaf(r, f, 1.0f);
  return r * __int_as_float(((int)nf + 127) << 23);
}

// ---------------- setup: init + dtype probe + class scatter (one CTA) ----------------
// JAX with x64 disabled silently stores int64-requested targets as int32.
// True LE int64 in [0,100) => every odd 32-bit word of the first BB words is 0.
__global__ void setup_kernel(const int* __restrict__ tgt32) {
  __shared__ int scnt[NCLS];
  __shared__ int nz;
  int tid = threadIdx.x;  // 1024

  for (int i = tid; i < NCLS; i += 1024) scnt[i] = 0;
  for (int i = tid; i < NCLS * NTP; i += 1024) g_partial[i] = 0.0f;
  if (tid == 0) nz = 0;
  __syncthreads();

  int c = 0;
  for (int i = tid; i < BB / 2; i += 1024)
    if (tgt32[2 * i + 1] != 0) c++;
  if (c) atomicAdd(&nz, 1);
  __syncthreads();
  int stride = (nz == 0) ? 2 : 1;   // 2 => int64 low words

  for (int i = tid; i < BB; i += 1024) {
    int cl = tgt32[(size_t)i * stride];
    if ((unsigned)cl < NCLS) {
      int s = atomicAdd(&scnt[cl], 1);
      if (s < CAP) g_list[cl * CAP + s] = i;
    }
  }
  __syncthreads();
  for (int i = tid; i < NCLS; i += 1024) g_cnt[i] = scnt[i];
}

// ---------------- softmax + t: one warp per row, shuffle-only reductions ----------------
__global__ void __launch_bounds__(256) softmax_kernel(const float* __restrict__ x) {
  int wid = threadIdx.x >> 5, lid = threadIdx.x & 31;
  int row = blockIdx.x * 8 + wid;

  const float4* src = reinterpret_cast<const float4*>(x + (size_t)row * CC);
  float y[32];
  float m = -3.4e38f;
#pragma unroll
  for (int q = 0; q < 8; q++) {
    float4 v = src[q * 32 + lid];
    y[4 * q + 0] = v.x * TINV; y[4 * q + 1] = v.y * TINV;
    y[4 * q + 2] = v.z * TINV; y[4 * q + 3] = v.w * TINV;
    m = fmaxf(m, fmaxf(fmaxf(y[4 * q], y[4 * q + 1]), fmaxf(y[4 * q + 2], y[4 * q + 3])));
  }
  m = warpMaxf(m);

  float e[32];
  float s = 0.0f;
#pragma unroll
  for (int i = 0; i < 32; i++) { e[i] = fast_exp(y[i] - m); s += e[i]; }
  s = warpSumf(s);
  float invS = 1.0f / s;
  float lnS  = __logf(s);

  uint2* dst = reinterpret_cast<uint2*>(g_pb + (size_t)row * CC);
  float tl = 0.0f;
#pragma unroll
  for (int q = 0; q < 8; q++) {
    float p0 = fmaf(e[4 * q + 0], invS, 1e-8f);
    float p1 = fmaf(e[4 * q + 1], invS, 1e-8f);
    float p2 = fmaf(e[4 * q + 2], invS, 1e-8f);
    float p3 = fmaf(e[4 * q + 3], invS, 1e-8f);
    // log p ~= y - m - lnS (+1e-8 shift perturbs log by ~1e-5 abs -> negligible)
    tl += p0 * (y[4 * q + 0] - m - lnS) + p1 * (y[4 * q + 1] - m - lnS)
        + p2 * (y[4 * q + 2] - m - lnS) + p3 * (y[4 * q + 3] - m - lnS);
    __nv_bfloat162 h01 = __floats2bfloat162_rn(p0, p1);
    __nv_bfloat162 h23 = __floats2bfloat162_rn(p2, p3);
    uint2 pk;
    pk.x = *reinterpret_cast<uint32_t*>(&h01);
    pk.y = *reinterpret_cast<uint32_t*>(&h23);
    dst[q * 32 + lid] = pk;
  }
  tl = warpSumf(tl);
  if (lid == 0) g_t[row] = tl * (1.0f / CC);
}

// ---------------- per-class Gram via warp-level bf16 HMMA ----------------
// One CTA per (class, 128-block pair). 8 warps; warp w owns rows [w*16, w*16+16)
// of the 128x128 D block. A/B tiles in smem, K chunked at 64 bf16, double-buffered.
__global__ void __launch_bounds__(256) gram_kernel() {
  int c = blockIdx.y, tp = blockIdx.x;
  int g = g_cnt[c];
  if (g > 256) g = 256;
  if (g < 2) return;
  int bi = (tp == 2) ? 1 : 0;
  int bj = (tp == 0) ? 0 : 1;
  int gA = min(g - bi * 128, 128);
  int gB = min(g - bj * 128, 128);
  if (gA <= 0 || gB <= 0) return;
  bool diag = (bi == bj);

  __shared__ __align__(1024) __nv_bfloat16 sT[2][128 * KC];  // 2 x 16 KB
  __shared__ int   sRA[128], sRB[128];
  __shared__ float sTA[128], sTB[128];

  int tid = threadIdx.x, wid = tid >> 5, lid = tid & 31;

  if (tid < 128) {
    int r = g_list[c * CAP + min(bi * 128 + tid, g - 1)];
    sRA[tid] = r; sTA[tid] = g_t[r];
  } else {
    int t2 = tid - 128;
    int r = g_list[c * CAP + min(bj * 128 + t2, g - 1)];
    sRB[t2] = r; sTB[t2] = g_t[r];
  }
  __syncthreads();

  // fixed per-thread load slots: 4 x (row, 16B granule) per tile
  const __nv_bfloat16* srcA[4];
  const __nv_bfloat16* srcB[4];
  uint32_t soff[4];
#pragma unroll
  for (int q = 0; q < 4; q++) {
    int s = tid + 256 * q;
    int row = s >> 3, gr = s & 7;
    srcA[q] = g_pb + (size_t)sRA[row] * CC + gr * 8;
    srcB[q] = g_pb + (size_t)sRB[row] * CC + gr * 8;
    soff[q] = swz((uint32_t)(row * 128 + gr * 16));
  }

  uint32_t st0 = smem_u32(&sT[0][0]);
  uint32_t st1 = smem_u32(&sT[1][0]);

  float acc[16][4];
#pragma unroll
  for (int i = 0; i < 16; i++)
#pragma unroll
    for (int j = 0; j < 4; j++) acc[i][j] = 0.0f;

  int  m0   = wid * 16;
  bool act  = (m0 < gA);
  int  nPair = (gB + 15) >> 4;   // 16-col tile pairs actually needed
  // ldmatrix lane address components (bytes within tile)
  uint32_t rowAb = (uint32_t)((m0 + (lid & 15)) * 128 + (lid >> 4) * 16);
  uint32_t rowBb = (uint32_t)(((lid & 7) + ((lid >> 4) << 3)) * 128 + ((lid >> 3) & 1) * 16);

  auto compute = [&](uint32_t aB, uint32_t bB) {
    if (!act) return;
#pragma unroll
    for (int kk = 0; kk < 4; kk++) {        // 4 k16 steps per 64-chunk
      uint32_t a0, a1, a2, a3;
      ldsm_x4(aB + swz(rowAb + kk * 32), a0, a1, a2, a3);
#pragma unroll
      for (int nt2 = 0; nt2 < 8; nt2++) {
        if (nt2 < nPair) {
          uint32_t b0, b1, b2, b3;
          ldsm_x4(bB + swz(rowBb + nt2 * 2048 + kk * 32), b0, b1, b2, b3);
          mma16816(acc[2 * nt2],     a0, a1, a2, a3, b0, b1);
          mma16816(acc[2 * nt2 + 1], a0, a1, a2, a3, b2, b3);
        }
      }
    }
  };

  if (diag) {
    // D = A.A^T: one tile, classic double buffer; mma.sync is warp-synchronous
#pragma unroll
    for (int q = 0; q < 4; q++) cpa16(st0 + soff[q], srcA[q]);
    cp_commit();
    for (int ch = 0; ch < NCHUNK; ch++) {
      uint32_t cur = (ch & 1) ? st1 : st0;
      if (ch + 1 < NCHUNK) {
        uint32_t nxt = (ch & 1) ? st0 : st1;
        int off = (ch + 1) * KC;
#pragma unroll
        for (int q = 0; q < 4; q++) cpa16(nxt + soff[q], srcA[q] + off);
        cp_commit();
        cp_wait<1>();
      } else {
        cp_wait<0>();
      }
      __syncthreads();
      compute(cur, cur);
      __syncthreads();   // stage consumed before refill next iteration
    }
  } else {
    // off-diagonal (class > 128 rows; rare): single-buffered A/B in the 2 stages
    for (int ch = 0; ch < NCHUNK; ch++) {
      int off = ch * KC;
#pragma unroll
      for (int q = 0; q < 4; q++) cpa16(st0 + soff[q], srcA[q] + off);
#pragma unroll
      for (int q = 0; q < 4; q++) cpa16(st1 + soff[q], srcB[q] + off);
      cp_commit();
      cp_wait<0>();
      __syncthreads();
      compute(st0, st1);
      __syncthreads();
    }
  }

  // epilogue: acc[nt] C-fragment: c0=(r0,n0), c1=(r0,n0+1), c2=(r1,n0), c3=(r1,n0+1)
  float local = 0.0f;
  if (act) {
    float inv = 1.0f / (float)CC;
    int gid = lid >> 2, tg = lid & 3;
    int r0 = m0 + gid, r1 = r0 + 8;
    float tA0 = sTA[r0], tA1 = sTA[r1];
    bool v0 = r0 < gA, v1 = r1 < gA;
#pragma unroll
    for (int nt = 0; nt < 16; nt++) {
      int n0 = nt * 8 + tg * 2;
#pragma unroll
      for (int e2 = 0; e2 < 4; e2++) {
        int  rr = (e2 & 2) ? r1 : r0;
        bool vr = (e2 & 2) ? v1 : v0;
        int  cl = n0 + (e2 & 1);
        if (vr && (cl < gB) && (!diag || rr != cl)) {
          float cross = acc[nt][e2] * inv;
          float d = sTB[cl] - cross;          // kl[row, col]
          local += d * d;
          if (!diag) {                        // also ordered pair (col, row)
            float d2 = ((e2 & 2) ? tA1 : tA0) - cross;
            local += d2 * d2;
          }
        }
      }
    }
  }
  local = warpSumf(local);
  __shared__ float rs[8];
  if (lid == 0) rs[wid] = local;
  __syncthreads();
  if (tid == 0) {
    float tot = 0.0f;
#pragma unroll
    for (int w = 0; w < 8; w++) tot += rs[w];
    g_partial[c * NTP + tp] = tot;
  }
}

// ---------------- final reduce (deterministic) ----------------
__global__ void final_kernel(float* __restrict__ out) {
  int tid = threadIdx.x;  // 128
  float s = 0.0f;
  for (int i = tid; i < NCLS * NTP; i += 128) s += g_partial[i];
  s = warpSumf(s);
  __shared__ float red[4];
  if ((tid & 31) == 0) red[tid >> 5] = s;
  __syncthreads();
  if (tid == 0) out[0] = (red[0] + red[1] + red[2] + red[3]) / (float)BB;
}

extern "C" void kernel_launch(void* const* d_in, const int* in_sizes, int n_in,
                              void* d_out, int out_size) {
  const float* x;
  const int* tgt32;
  if (in_sizes[0] == BB) {       // defensive input-order detection
    tgt32 = (const int*)d_in[0];
    x     = (const float*)d_in[1];
  } else {
    x     = (const float*)d_in[0];
    tgt32 = (const int*)d_in[1];
  }

  setup_kernel<<<1, 1024>>>(tgt32);
  softmax_kernel<<<BB / 8, 256>>>(x);
  dim3 gg(NTP, NCLS);
  gram_kernel<<<gg, 256>>>();
  final_kernel<<<1, 128>>>((float*)d_out);
}

// round 6
// speedup vs baseline: 3.3590x; 1.0617x over previous
#include <cuda_runtime.h>
#include <cuda_bf16.h>
#include <cstdint>

#define BB    8192
#define CC    1024
#define NCLS  100
#define CAP   1024
#define NTP   3          // block pairs (0,0),(0,1),(1,1): class size <= 256
#define NCTA  (NCLS * NTP)
#define TINV  0.25f      // 1/T, T=4
#define KC    64         // bf16 per K-chunk (128 bytes/row)
#define NCHUNK (CC / KC) // 16

// ---- scratch (device globals: no allocations allowed) ----
__device__ __nv_bfloat16 g_pb[(size_t)BB * CC];   // 16 MB bf16 probs
__device__ float g_t[BB];
__device__ int   g_cnt[NCLS];
__device__ int   g_list[NCLS * CAP];
__device__ float g_partial[NCTA];
__device__ int   g_done = 0;                      // reset by last CTA each run

// ---- helpers ----
__device__ __forceinline__ uint32_t smem_u32(const void* p) {
  uint32_t a;
  asm("{ .reg .u64 t; cvta.to.shared.u64 t, %1; cvt.u32.u64 %0, t; }" : "=r"(a) : "l"(p));
  return a;
}
__device__ __forceinline__ void cpa16(uint32_t smem_dst, const void* gsrc) {
  asm volatile("cp.async.cg.shared.global [%0], [%1], 16;" :: "r"(smem_dst), "l"(gsrc));
}
__device__ __forceinline__ void cp_commit() { asm volatile("cp.async.commit_group;"); }
template <int N> __device__ __forceinline__ void cp_wait() {
  asm volatile("cp.async.wait_group %0;" :: "n"(N));
}
__device__ __forceinline__ uint32_t swz(uint32_t b) { return b ^ ((b >> 3) & 0x70); }

__device__ __forceinline__ void ldsm_x4(uint32_t a, uint32_t& r0, uint32_t& r1,
                                        uint32_t& r2, uint32_t& r3) {
  asm volatile("ldmatrix.sync.aligned.m8n8.x4.shared.b16 {%0,%1,%2,%3}, [%4];"
               : "=r"(r0), "=r"(r1), "=r"(r2), "=r"(r3) : "r"(a));
}
__device__ __forceinline__ void mma16816(float* c, uint32_t a0, uint32_t a1,
                                         uint32_t a2, uint32_t a3,
                                         uint32_t b0, uint32_t b1) {
  asm volatile(
      "mma.sync.aligned.m16n8k16.row.col.f32.bf16.bf16.f32 "
      "{%0,%1,%2,%3}, {%4,%5,%6,%7}, {%8,%9}, {%0,%1,%2,%3};"
      : "+f"(c[0]), "+f"(c[1]), "+f"(c[2]), "+f"(c[3])
      : "r"(a0), "r"(a1), "r"(a2), "r"(a3), "r"(b0), "r"(b1));
}

__device__ __forceinline__ float warpMaxf(float v) {
#pragma unroll
  for (int o = 16; o > 0; o >>= 1) v = fmaxf(v, __shfl_xor_sync(0xffffffffu, v, o));
  return v;
}
__device__ __forceinline__ float warpSumf(float v) {
#pragma unroll
  for (int o = 16; o > 0; o >>= 1) v += __shfl_xor_sync(0xffffffffu, v, o);
  return v;
}

// exp(z) for z <= 0 via 2^w with degree-7 poly: FMA pipe only, avoids MUFU.EX2.
__device__ __forceinline__ float fast_exp(float z) {
  float w  = z * 1.4426950408889634f;
  float nf = floorf(w);
  float f  = w - nf;
  float r  = 1.5252733e-5f;
  r = fmaf(r, f, 1.5403530e-4f);
  r = fmaf(r, f, 1.3333558e-3f);
  r = fmaf(r, f, 9.6181291e-3f);
  r = fmaf(r, f, 5.5504109e-2f);
  r = fmaf(r, f, 2.4022651e-1f);
  r = fmaf(r, f, 6.9314718e-1f);
  r = fmaf(r, f, 1.0f);
  return r * __int_as_float(((int)nf + 127) << 23);
}

// ---- setup (runs inside softmax CTA 0): dtype probe + class scatter ----
// JAX with x64 disabled silently stores int64-requested targets as int32.
// True LE int64 in [0,100) => every odd 32-bit word of the first BB words is 0.
__device__ __forceinline__ void do_setup(const int* __restrict__ tgt32, int tid) {
  __shared__ int scnt[NCLS];
  __shared__ int nz;
  for (int i = tid; i < NCLS; i += 256) scnt[i] = 0;
  if (tid == 0) nz = 0;
  __syncthreads();

  int c = 0;
  for (int i = tid; i < BB / 2; i += 256)
    if (tgt32[2 * i + 1] != 0) c++;
  if (c) atomicAdd(&nz, 1);
  __syncthreads();
  int stride = (nz == 0) ? 2 : 1;   // 2 => int64 low words

  for (int i = tid; i < BB; i += 256) {
    int cl = tgt32[(size_t)i * stride];
    if ((unsigned)cl < NCLS) {
      int s = atomicAdd(&scnt[cl], 1);
      if (s < CAP) g_list[cl * CAP + s] = i;
    }
  }
  __syncthreads();
  for (int i = tid; i < NCLS; i += 256) g_cnt[i] = scnt[i];
}

// ---------------- softmax + t (warp per row) + embedded setup in CTA 0 ----------------
__global__ void __launch_bounds__(256) softmax_kernel(const float* __restrict__ x,
                                                      const int* __restrict__ tgt32) {
  if (blockIdx.x == 0) do_setup(tgt32, threadIdx.x);

  int wid = threadIdx.x >> 5, lid = threadIdx.x & 31;
  int row = blockIdx.x * 8 + wid;

  const float4* src = reinterpret_cast<const float4*>(x + (size_t)row * CC);
  float y[32];
  float m = -3.4e38f;
#pragma unroll
  for (int q = 0; q < 8; q++) {
    float4 v = src[q * 32 + lid];
    y[4 * q + 0] = v.x * TINV; y[4 * q + 1] = v.y * TINV;
    y[4 * q + 2] = v.z * TINV; y[4 * q + 3] = v.w * TINV;
    m = fmaxf(m, fmaxf(fmaxf(y[4 * q], y[4 * q + 1]), fmaxf(y[4 * q + 2], y[4 * q + 3])));
  }
  m = warpMaxf(m);

  float e[32];
  float s = 0.0f;
#pragma unroll
  for (int i = 0; i < 32; i++) { e[i] = fast_exp(y[i] - m); s += e[i]; }
  s = warpSumf(s);
  float invS = 1.0f / s;
  float lnS  = __logf(s);

  uint2* dst = reinterpret_cast<uint2*>(g_pb + (size_t)row * CC);
  float tl = 0.0f;
#pragma unroll
  for (int q = 0; q < 8; q++) {
    float p0 = fmaf(e[4 * q + 0], invS, 1e-8f);
    float p1 = fmaf(e[4 * q + 1], invS, 1e-8f);
    float p2 = fmaf(e[4 * q + 2], invS, 1e-8f);
    float p3 = fmaf(e[4 * q + 3], invS, 1e-8f);
    // log p ~= y - m - lnS (+1e-8 shift perturbs log by ~1e-5 abs -> negligible)
    tl += p0 * (y[4 * q + 0] - m - lnS) + p1 * (y[4 * q + 1] - m - lnS)
        + p2 * (y[4 * q + 2] - m - lnS) + p3 * (y[4 * q + 3] - m - lnS);
    __nv_bfloat162 h01 = __floats2bfloat162_rn(p0, p1);
    __nv_bfloat162 h23 = __floats2bfloat162_rn(p2, p3);
    uint2 pk;
    pk.x = *reinterpret_cast<uint32_t*>(&h01);
    pk.y = *reinterpret_cast<uint32_t*>(&h23);
    dst[q * 32 + lid] = pk;
  }
  tl = warpSumf(tl);
  if (lid == 0) g_t[row] = tl * (1.0f / CC);
}

// ---------------- per-class Gram via warp-level bf16 HMMA + fused final reduce ------
// One CTA per (class, 128-block pair). 8 warps; warp w owns rows [w*16, w*16+16)
// of the 128x128 D block. A/B tiles in smem, K chunked at 64 bf16, double-buffered.
// Last CTA to finish reduces g_partial into d_out (deterministic fixed-order sum).
__global__ void __launch_bounds__(256) gram_kernel(float* __restrict__ out) {
  int c = blockIdx.y, tp = blockIdx.x;
  int g = g_cnt[c];
  if (g > 256) g = 256;
  int bi = (tp == 2) ? 1 : 0;
  int bj = (tp == 0) ? 0 : 1;
  int gA = min(g - bi * 128, 128);
  int gB = min(g - bj * 128, 128);
  bool diag = (bi == bj);
  bool active = (g >= 2) && (gA > 0) && (gB > 0);

  __shared__ __align__(1024) __nv_bfloat16 sT[2][128 * KC];  // 2 x 16 KB
  __shared__ int   sRA[128], sRB[128];
  __shared__ float sTA[128], sTB[128];
  __shared__ float rs[8];
  __shared__ int   sLast;

  int tid = threadIdx.x, wid = tid >> 5, lid = tid & 31;
  float total = 0.0f;

  if (active) {
    if (tid < 128) {
      int r = g_list[c * CAP + min(bi * 128 + tid, g - 1)];
      sRA[tid] = r; sTA[tid] = g_t[r];
    } else {
      int t2 = tid - 128;
      int r = g_list[c * CAP + min(bj * 128 + t2, g - 1)];
      sRB[t2] = r; sTB[t2] = g_t[r];
    }
    __syncthreads();

    // fixed per-thread load slots: 4 x (row, 16B granule) per tile
    const __nv_bfloat16* srcA[4];
    const __nv_bfloat16* srcB[4];
    uint32_t soff[4];
#pragma unroll
    for (int q = 0; q < 4; q++) {
      int s = tid + 256 * q;
      int row = s >> 3, gr = s & 7;
      srcA[q] = g_pb + (size_t)sRA[row] * CC + gr * 8;
      srcB[q] = g_pb + (size_t)sRB[row] * CC + gr * 8;
      soff[q] = swz((uint32_t)(row * 128 + gr * 16));
    }

    uint32_t st0 = smem_u32(&sT[0][0]);
    uint32_t st1 = smem_u32(&sT[1][0]);

    float acc[16][4];
#pragma unroll
    for (int i = 0; i < 16; i++)
#pragma unroll
      for (int j = 0; j < 4; j++) acc[i][j] = 0.0f;

    int  m0    = wid * 16;
    bool act   = (m0 < gA);
    int  nPair = (gB + 15) >> 4;   // 16-col tile pairs actually needed
    uint32_t rowAb = (uint32_t)((m0 + (lid & 15)) * 128 + (lid >> 4) * 16);
    uint32_t rowBb = (uint32_t)(((lid & 7) + ((lid >> 4) << 3)) * 128 + ((lid >> 3) & 1) * 16);

    auto compute = [&](uint32_t aB, uint32_t bB) {
      if (!act) return;
#pragma unroll
      for (int kk = 0; kk < 4; kk++) {        // 4 k16 steps per 64-chunk
        uint32_t a0, a1, a2, a3;
        ldsm_x4(aB + swz(rowAb + kk * 32), a0, a1, a2, a3);
#pragma unroll
        for (int nt2 = 0; nt2 < 8; nt2++) {
          if (nt2 < nPair) {
            uint32_t b0, b1, b2, b3;
            ldsm_x4(bB + swz(rowBb + nt2 * 2048 + kk * 32), b0, b1, b2, b3);
            mma16816(acc[2 * nt2],     a0, a1, a2, a3, b0, b1);
            mma16816(acc[2 * nt2 + 1], a0, a1, a2, a3, b2, b3);
          }
        }
      }
    };

    if (diag) {
      // D = A.A^T: one tile, classic double buffer; mma.sync is warp-synchronous
#pragma unroll
      for (int q = 0; q < 4; q++) cpa16(st0 + soff[q], srcA[q]);
      cp_commit();
      for (int ch = 0; ch < NCHUNK; ch++) {
        uint32_t cur = (ch & 1) ? st1 : st0;
        if (ch + 1 < NCHUNK) {
          uint32_t nxt = (ch & 1) ? st0 : st1;
          int off = (ch + 1) * KC;
#pragma unroll
          for (int q = 0; q < 4; q++) cpa16(nxt + soff[q], srcA[q] + off);
          cp_commit();
          cp_wait<1>();
        } else {
          cp_wait<0>();
        }
        __syncthreads();
        compute(cur, cur);
        __syncthreads();   // stage consumed before refill next iteration
      }
    } else {
      // off-diagonal (class > 128 rows; rare): single-buffered A/B in the 2 stages
      for (int ch = 0; ch < NCHUNK; ch++) {
        int off = ch * KC;
#pragma unroll
        for (int q = 0; q < 4; q++) cpa16(st0 + soff[q], srcA[q] + off);
#pragma unroll
        for (int q = 0; q < 4; q++) cpa16(st1 + soff[q], srcB[q] + off);
        cp_commit();
        cp_wait<0>();
        __syncthreads();
        compute(st0, st1);
        __syncthreads();
      }
    }

    // epilogue: acc[nt] C-fragment: c0=(r0,n0), c1=(r0,n0+1), c2=(r1,n0), c3=(r1,n0+1)
    float local = 0.0f;
    if (act) {
      float inv = 1.0f / (float)CC;
      int gid = lid >> 2, tg = lid & 3;
      int r0 = m0 + gid, r1 = r0 + 8;
      float tA0 = sTA[r0], tA1 = sTA[r1];
      bool v0 = r0 < gA, v1 = r1 < gA;
#pragma unroll
      for (int nt = 0; nt < 16; nt++) {
        int n0 = nt * 8 + tg * 2;
#pragma unroll
        for (int e2 = 0; e2 < 4; e2++) {
          int  rr = (e2 & 2) ? r1 : r0;
          bool vr = (e2 & 2) ? v1 : v0;
          int  cl = n0 + (e2 & 1);
          if (vr && (cl < gB) && (!diag || rr != cl)) {
            float cross = acc[nt][e2] * inv;
            float d = sTB[cl] - cross;          // kl[row, col]
            local += d * d;
            if (!diag) {                        // also ordered pair (col, row)
              float d2 = ((e2 & 2) ? tA1 : tA0) - cross;
              local += d2 * d2;
            }
          }
        }
      }
    }
    local = warpSumf(local);
    if (lid == 0) rs[wid] = local;
    __syncthreads();
    if (tid == 0) {
#pragma unroll
      for (int w = 0; w < 8; w++) total += rs[w];
    }
  }

  // ---- publish partial, then last-CTA-done final reduce ----
  if (tid == 0) {
    g_partial[c * NTP + tp] = total;
    __threadfence();
    int old = atomicAdd(&g_done, 1);
    sLast = (old == NCTA - 1) ? 1 : 0;
  }
  __syncthreads();
  if (sLast) {
    float s = 0.0f;
    for (int i = tid; i < NCTA; i += 256) s += g_partial[i];
    s = warpSumf(s);
    if (lid == 0) rs[wid] = s;
    __syncthreads();
    if (tid == 0) {
      float tot = 0.0f;
#pragma unroll
      for (int w = 0; w < 8; w++) tot += rs[w];
      out[0] = tot / (float)BB;
      g_done = 0;             // reset for next graph replay
    }
  }
}

extern "C" void kernel_launch(void* const* d_in, const int* in_sizes, int n_in,
                              void* d_out, int out_size) {
  const float* x;
  const int* tgt32;
  if (in_sizes[0] == BB) {       // defensive input-order detection
    tgt32 = (const int*)d_in[0];
    x     = (const float*)d_in[1];
  } else {
    x     = (const float*)d_in[0];
    tgt32 = (const int*)d_in[1];
  }

  softmax_kernel<<<BB / 8, 256>>>(x, tgt32);
  dim3 gg(NTP, NCLS);
  gram_kernel<<<gg, 256>>>((float*)d_out);
}